// round 1
// baseline (speedup 1.0000x reference)
#include <cuda_runtime.h>
#include <math.h>

// Problem constants (fixed shapes from reference)
#define BATCH 2
#define SEQ   2048
#define EMB   1024
#define HEADS 16
#define HDIM  64          // EMB / HEADS
#define M_TOT (BATCH * SEQ)   // 4096
#define QKV_N (3 * EMB)       // 3072

// Scratch (device globals; no allocation allowed in kernel_launch)
__device__ float g_qkv[M_TOT * QKV_N];      // [B,N,3,H,D]  ~50 MB
__device__ float g_attn[M_TOT * EMB];       // [B,N,C]      ~16 MB

// ---------------------------------------------------------------------------
// Tiled fp32 GEMM: C[M,N] = A[M,K] @ B[K,N] + bias[N]
// Block tile 64x64, K tile 16. 256 threads, each computes 4x4.
// ---------------------------------------------------------------------------
__global__ __launch_bounds__(256)
void gemm_bias_kernel(const float* __restrict__ A,
                      const float* __restrict__ B,
                      const float* __restrict__ bias,
                      float* __restrict__ C,
                      int M, int N, int K) {
    __shared__ float As[16][68];   // transposed: As[k][m], padded for bank/align
    __shared__ float Bs[16][64];   // Bs[k][n]

    const int tid = threadIdx.x;
    const int tx = tid & 15;       // 0..15 -> n sub-tile
    const int ty = tid >> 4;       // 0..15 -> m sub-tile
    const int m0 = blockIdx.y * 64;
    const int n0 = blockIdx.x * 64;

    // load mapping
    const int a_row = tid >> 2;    // 0..63
    const int a_seg = tid & 3;     // 0..3  (4 k-values each)
    const int b_k   = tid >> 4;    // 0..15
    const int b_seg = tid & 15;    // 0..15 (4 n-values each)

    float acc[4][4];
#pragma unroll
    for (int i = 0; i < 4; i++)
#pragma unroll
        for (int j = 0; j < 4; j++) acc[i][j] = 0.0f;

    for (int k0 = 0; k0 < K; k0 += 16) {
        float4 av = *(const float4*)&A[(size_t)(m0 + a_row) * K + k0 + a_seg * 4];
        As[a_seg * 4 + 0][a_row] = av.x;
        As[a_seg * 4 + 1][a_row] = av.y;
        As[a_seg * 4 + 2][a_row] = av.z;
        As[a_seg * 4 + 3][a_row] = av.w;
        *(float4*)&Bs[b_k][b_seg * 4] =
            *(const float4*)&B[(size_t)(k0 + b_k) * N + n0 + b_seg * 4];
        __syncthreads();

#pragma unroll
        for (int kk = 0; kk < 16; kk++) {
            float4 a = *(const float4*)&As[kk][ty * 4];
            float4 b = *(const float4*)&Bs[kk][tx * 4];
            acc[0][0] += a.x * b.x; acc[0][1] += a.x * b.y;
            acc[0][2] += a.x * b.z; acc[0][3] += a.x * b.w;
            acc[1][0] += a.y * b.x; acc[1][1] += a.y * b.y;
            acc[1][2] += a.y * b.z; acc[1][3] += a.y * b.w;
            acc[2][0] += a.z * b.x; acc[2][1] += a.z * b.y;
            acc[2][2] += a.z * b.z; acc[2][3] += a.z * b.w;
            acc[3][0] += a.w * b.x; acc[3][1] += a.w * b.y;
            acc[3][2] += a.w * b.z; acc[3][3] += a.w * b.w;
        }
        __syncthreads();
    }

#pragma unroll
    for (int i = 0; i < 4; i++) {
        const int row = m0 + ty * 4 + i;
#pragma unroll
        for (int j = 0; j < 4; j++) {
            const int col = n0 + tx * 4 + j;
            C[(size_t)row * N + col] = acc[i][j] + bias[col];
        }
    }
}

// ---------------------------------------------------------------------------
// Flash-style attention over g_qkv (layout [B,N,3,H,D]).
// Grid: (SEQ/64, BATCH*HEADS). Block 256 threads.
// Query tile Br=64, key tile Bc=32. Output -> g_attn in [B,N,C] layout.
// ---------------------------------------------------------------------------
__global__ __launch_bounds__(256)
void attn_kernel(const float* __restrict__ qkv, float* __restrict__ out) {
    __shared__ float Qs[64][68];
    __shared__ float Ks[32][68];
    __shared__ float Vs[32][68];
    __shared__ float Ps[64][36];

    const int bh = blockIdx.y;
    const int b  = bh / HEADS;
    const int h  = bh % HEADS;
    const int q0 = blockIdx.x * 64;

    const int tid = threadIdx.x;
    const int tx = tid & 15;   // 0..15
    const int ty = tid >> 4;   // 0..15

    // base offset for (b, n=0, part=0, h, d=0)
    const size_t base = (size_t)b * SEQ * 3 * EMB + (size_t)h * HDIM;
    const size_t rowstride = 3 * EMB;  // stride between n and n+1

    // Load Q tile: 64 rows x 64 d = 1024 float4s, 4 per thread
    for (int i = tid; i < 64 * 16; i += 256) {
        int r = i >> 4, s = i & 15;
        *(float4*)&Qs[r][s * 4] =
            *(const float4*)&qkv[base + (size_t)(q0 + r) * rowstride + s * 4];
    }

    float m[4], l[4], acc[4][4];
#pragma unroll
    for (int i = 0; i < 4; i++) {
        m[i] = -INFINITY;
        l[i] = 0.0f;
#pragma unroll
        for (int j = 0; j < 4; j++) acc[i][j] = 0.0f;
    }

    const float scale = 0.03125f;  // EMB^-0.5 = 1/32 (full embed dim per reference!)

    for (int k0 = 0; k0 < SEQ; k0 += 32) {
        __syncthreads();  // previous iteration done reading Ks/Vs
        // Load K,V tiles: 32 rows x 16 float4 each -> 2 float4 per thread each
        for (int i = tid; i < 32 * 16; i += 256) {
            int r = i >> 4, s = i & 15;
            size_t roff = base + (size_t)(k0 + r) * rowstride;
            *(float4*)&Ks[r][s * 4] = *(const float4*)&qkv[roff + EMB + s * 4];
            *(float4*)&Vs[r][s * 4] = *(const float4*)&qkv[roff + 2 * EMB + s * 4];
        }
        __syncthreads();

        // S tile: rows ty*4+i, cols tx*2+c
        float s0[4], s1[4];
#pragma unroll
        for (int i = 0; i < 4; i++) { s0[i] = 0.0f; s1[i] = 0.0f; }
#pragma unroll 4
        for (int d = 0; d < 64; d++) {
            float k0v = Ks[tx * 2 + 0][d];
            float k1v = Ks[tx * 2 + 1][d];
#pragma unroll
            for (int i = 0; i < 4; i++) {
                float q = Qs[ty * 4 + i][d];
                s0[i] += q * k0v;
                s1[i] += q * k1v;
            }
        }

        // Online softmax update per row
#pragma unroll
        for (int i = 0; i < 4; i++) {
            s0[i] *= scale;
            s1[i] *= scale;
            float tmax = fmaxf(s0[i], s1[i]);
#pragma unroll
            for (int off = 8; off >= 1; off >>= 1)
                tmax = fmaxf(tmax, __shfl_xor_sync(0xffffffffu, tmax, off, 16));
            float m_new = fmaxf(m[i], tmax);
            float f = __expf(m[i] - m_new);
            float p0 = __expf(s0[i] - m_new);
            float p1 = __expf(s1[i] - m_new);
            float rs = p0 + p1;
#pragma unroll
            for (int off = 8; off >= 1; off >>= 1)
                rs += __shfl_xor_sync(0xffffffffu, rs, off, 16);
            l[i] = l[i] * f + rs;
            m[i] = m_new;
#pragma unroll
            for (int j = 0; j < 4; j++) acc[i][j] *= f;
            Ps[ty * 4 + i][tx * 2 + 0] = p0;
            Ps[ty * 4 + i][tx * 2 + 1] = p1;
        }
        __syncthreads();

        // acc += P[64x32] @ V[32x64]; thread tile rows ty*4+i, cols tx*4+j
#pragma unroll 8
        for (int j = 0; j < 32; j++) {
            float4 v = *(const float4*)&Vs[j][tx * 4];
            float p0v = Ps[ty * 4 + 0][j];
            float p1v = Ps[ty * 4 + 1][j];
            float p2v = Ps[ty * 4 + 2][j];
            float p3v = Ps[ty * 4 + 3][j];
            acc[0][0] += p0v * v.x; acc[0][1] += p0v * v.y; acc[0][2] += p0v * v.z; acc[0][3] += p0v * v.w;
            acc[1][0] += p1v * v.x; acc[1][1] += p1v * v.y; acc[1][2] += p1v * v.z; acc[1][3] += p1v * v.w;
            acc[2][0] += p2v * v.x; acc[2][1] += p2v * v.y; acc[2][2] += p2v * v.z; acc[2][3] += p2v * v.w;
            acc[3][0] += p3v * v.x; acc[3][1] += p3v * v.y; acc[3][2] += p3v * v.z; acc[3][3] += p3v * v.w;
        }
    }

    // Normalize and write to [B,N,C] layout: out[(b*SEQ+n)*EMB + h*64 + d]
#pragma unroll
    for (int i = 0; i < 4; i++) {
        const int n = q0 + ty * 4 + i;
        const float inv_l = 1.0f / l[i];
        size_t o = ((size_t)b * SEQ + n) * EMB + h * HDIM + tx * 4;
        float4 r;
        r.x = acc[i][0] * inv_l;
        r.y = acc[i][1] * inv_l;
        r.z = acc[i][2] * inv_l;
        r.w = acc[i][3] * inv_l;
        *(float4*)&out[o] = r;
    }
}

// ---------------------------------------------------------------------------
extern "C" void kernel_launch(void* const* d_in, const int* in_sizes, int n_in,
                              void* d_out, int out_size) {
    const float* x     = (const float*)d_in[0];   // [2,2048,1024]
    const float* W_qkv = (const float*)d_in[1];   // [1024,3072]
    const float* b_qkv = (const float*)d_in[2];   // [3072]
    const float* W_out = (const float*)d_in[3];   // [1024,1024]
    const float* b_out = (const float*)d_in[4];   // [1024]
    float* out = (float*)d_out;                   // [2,2048,1024]

    float* qkv;
    float* attn;
    cudaGetSymbolAddress((void**)&qkv, g_qkv);
    cudaGetSymbolAddress((void**)&attn, g_attn);

    // 1) QKV projection: [4096,1024] @ [1024,3072] + b_qkv
    {
        dim3 grid(QKV_N / 64, M_TOT / 64);
        gemm_bias_kernel<<<grid, 256>>>(x, W_qkv, b_qkv, qkv, M_TOT, QKV_N, EMB);
    }
    // 2) Attention
    {
        dim3 grid(SEQ / 64, BATCH * HEADS);
        attn_kernel<<<grid, 256>>>(qkv, attn);
    }
    // 3) Output projection: [4096,1024] @ [1024,1024] + b_out
    {
        dim3 grid(EMB / 64, M_TOT / 64);
        gemm_bias_kernel<<<grid, 256>>>(attn, W_out, b_out, out, M_TOT, EMB, EMB);
    }
}

// round 2
// speedup vs baseline: 2.6634x; 2.6634x over previous
#include <cuda_runtime.h>
#include <math.h>
#include <stdint.h>

#define BATCH 2
#define SEQ   2048
#define EMB   1024
#define HEADS 16
#define HDIM  64
#define M_TOT (BATCH * SEQ)   // 4096
#define QKV_N (3 * EMB)       // 3072

// Scratch (device globals; no allocation allowed)
__device__ float g_qkv[M_TOT * QKV_N];      // [B,N,3,H,D]
__device__ float g_attn[M_TOT * EMB];       // [B,N,C]

// ---------------------------------------------------------------------------
// helpers
// ---------------------------------------------------------------------------
__device__ __forceinline__ float to_tf32(float x) {
    uint32_t r;
    asm("cvt.rna.tf32.f32 %0, %1;" : "=r"(r) : "r"(__float_as_uint(x)));
    return __uint_as_float(r);
}

// D = A(16x8 tf32, row) * B(8x8 tf32, col) + D, fp32 accum
__device__ __forceinline__ void mma_tf32(float* c, const float* a, const float* b) {
    const uint32_t* A = (const uint32_t*)a;
    const uint32_t* B = (const uint32_t*)b;
    asm volatile(
        "mma.sync.aligned.m16n8k8.row.col.f32.tf32.tf32.f32 "
        "{%0,%1,%2,%3},{%4,%5,%6,%7},{%8,%9},{%0,%1,%2,%3};"
        : "+f"(c[0]), "+f"(c[1]), "+f"(c[2]), "+f"(c[3])
        : "r"(A[0]), "r"(A[1]), "r"(A[2]), "r"(A[3]), "r"(B[0]), "r"(B[1]));
}

// ---------------------------------------------------------------------------
// TF32 GEMM: C[M,N] = A[M,K] @ B[K,N] + bias
// block tile 128x128, K-tile 16, 256 threads = 8 warps (4 in M x 2 in N),
// warp tile 32x64 = (2 x 8) m16n8 mma tiles.
// ---------------------------------------------------------------------------
#define AS_STRIDE 20    // 16 + 4 pad: fragment reads conflict-free
#define BS_STRIDE 136   // 128 + 8 pad: fragment reads conflict-free

__global__ __launch_bounds__(256, 2)
void gemm_tf32_kernel(const float* __restrict__ A, const float* __restrict__ B,
                      const float* __restrict__ bias, float* __restrict__ C,
                      int M, int N, int K) {
    __shared__ float As[128 * AS_STRIDE];
    __shared__ float Bs[16 * BS_STRIDE];

    const int tid  = threadIdx.x;
    const int lane = tid & 31;
    const int warp = tid >> 5;
    const int wm = (warp >> 1) * 32;   // 0,32,64,96
    const int wn = (warp & 1) * 64;    // 0,64
    const int m0 = blockIdx.y * 128;
    const int n0 = blockIdx.x * 128;

    const int lg = lane >> 2;          // 0..7  (group)
    const int lt = lane & 3;           // 0..3  (thread in group)

    float c[2][8][4];
#pragma unroll
    for (int mi = 0; mi < 2; mi++)
#pragma unroll
        for (int ni = 0; ni < 8; ni++)
#pragma unroll
            for (int j = 0; j < 4; j++) c[mi][ni][j] = 0.0f;

    for (int k0 = 0; k0 < K; k0 += 16) {
        // ---- load A tile 128x16 (2 float4 per thread) ----
#pragma unroll
        for (int r = 0; r < 2; r++) {
            int i = tid + r * 256;
            int row = i >> 2, seg = i & 3;
            float4 v = *(const float4*)&A[(size_t)(m0 + row) * K + k0 + seg * 4];
            float* d = &As[row * AS_STRIDE + seg * 4];
            d[0] = to_tf32(v.x); d[1] = to_tf32(v.y);
            d[2] = to_tf32(v.z); d[3] = to_tf32(v.w);
        }
        // ---- load B tile 16x128 (2 float4 per thread) ----
#pragma unroll
        for (int r = 0; r < 2; r++) {
            int i = tid + r * 256;
            int row = i >> 5, seg = i & 31;
            float4 v = *(const float4*)&B[(size_t)(k0 + row) * N + n0 + seg * 4];
            float* d = &Bs[row * BS_STRIDE + seg * 4];
            d[0] = to_tf32(v.x); d[1] = to_tf32(v.y);
            d[2] = to_tf32(v.z); d[3] = to_tf32(v.w);
        }
        __syncthreads();

#pragma unroll
        for (int ks = 0; ks < 2; ks++) {
            const int kk = ks * 8;
            float a[2][4];
#pragma unroll
            for (int mi = 0; mi < 2; mi++) {
                int row = wm + mi * 16 + lg;
                int col = kk + lt;
                a[mi][0] = As[row * AS_STRIDE + col];
                a[mi][1] = As[(row + 8) * AS_STRIDE + col];
                a[mi][2] = As[row * AS_STRIDE + col + 4];
                a[mi][3] = As[(row + 8) * AS_STRIDE + col + 4];
            }
#pragma unroll
            for (int ni = 0; ni < 8; ni++) {
                float bfr[2];
                int col = wn + ni * 8 + lg;
                bfr[0] = Bs[(kk + lt) * BS_STRIDE + col];
                bfr[1] = Bs[(kk + lt + 4) * BS_STRIDE + col];
                mma_tf32(c[0][ni], a[0], bfr);
                mma_tf32(c[1][ni], a[1], bfr);
            }
        }
        __syncthreads();
    }

    // ---- epilogue: bias + store ----
#pragma unroll
    for (int mi = 0; mi < 2; mi++) {
        int row = m0 + wm + mi * 16 + lg;
#pragma unroll
        for (int ni = 0; ni < 8; ni++) {
            int col = n0 + wn + ni * 8 + 2 * lt;
            float2 bv = *(const float2*)&bias[col];
            float2 r0 = make_float2(c[mi][ni][0] + bv.x, c[mi][ni][1] + bv.y);
            float2 r1 = make_float2(c[mi][ni][2] + bv.x, c[mi][ni][3] + bv.y);
            *(float2*)&C[(size_t)row * N + col] = r0;
            *(float2*)&C[(size_t)(row + 8) * N + col] = r1;
        }
    }
}

// ---------------------------------------------------------------------------
// Flash attention, TF32 tensor cores.
// Grid (SEQ/128, B*H), 256 threads = 8 warps, each warp owns 16 query rows.
// Br = 128, Bc = 64. Q fragments live in registers, P routed via per-warp smem.
// ---------------------------------------------------------------------------
#define KS_STRIDE 68
#define VS_STRIDE 72
#define PS_STRIDE 68
#define KS_FLOATS (64 * KS_STRIDE)
#define VS_FLOATS (64 * VS_STRIDE)
#define PS_FLOATS (128 * PS_STRIDE)
#define ATTN_SMEM_BYTES ((KS_FLOATS + VS_FLOATS + PS_FLOATS) * 4)

__global__ __launch_bounds__(256, 1)
void attn_tf32_kernel(const float* __restrict__ qkv, float* __restrict__ out) {
    extern __shared__ float sm[];
    float* Ks = sm;                       // [64][68] tf32
    float* Vs = sm + KS_FLOATS;           // [64][72] tf32
    float* Ps = sm + KS_FLOATS + VS_FLOATS; // [128][68] (Q staging, then P)

    const int tid  = threadIdx.x;
    const int lane = tid & 31;
    const int warp = tid >> 5;
    const int lg = lane >> 2;    // 0..7
    const int lt = lane & 3;     // 0..3
    const int bh = blockIdx.y;
    const int b  = bh >> 4;
    const int h  = bh & 15;
    const int q0 = blockIdx.x * 128;

    const size_t base = (size_t)b * SEQ * 3 * EMB + (size_t)h * HDIM;

    // ---- stage Q tile (128x64) into Ps region, tf32-converted ----
    for (int i = tid; i < 128 * 16; i += 256) {
        int row = i >> 4, seg = i & 15;
        float4 v = *(const float4*)&qkv[base + (size_t)(q0 + row) * 3072 + seg * 4];
        float* d = &Ps[row * PS_STRIDE + seg * 4];
        d[0] = to_tf32(v.x); d[1] = to_tf32(v.y);
        d[2] = to_tf32(v.z); d[3] = to_tf32(v.w);
    }
    __syncthreads();

    // ---- extract Q A-fragments (warp's 16 rows x 64 d) ----
    float aq[8][4];
    {
        int r = warp * 16 + lg;
#pragma unroll
        for (int kd = 0; kd < 8; kd++) {
            int col = kd * 8 + lt;
            aq[kd][0] = Ps[r * PS_STRIDE + col];
            aq[kd][1] = Ps[(r + 8) * PS_STRIDE + col];
            aq[kd][2] = Ps[r * PS_STRIDE + col + 4];
            aq[kd][3] = Ps[(r + 8) * PS_STRIDE + col + 4];
        }
    }

    float o[8][4];
#pragma unroll
    for (int ni = 0; ni < 8; ni++)
#pragma unroll
        for (int j = 0; j < 4; j++) o[ni][j] = 0.0f;
    float m0r = -INFINITY, m1r = -INFINITY, l0 = 0.0f, l1 = 0.0f;
    const float scale = 0.03125f;  // EMB^-0.5 (reference scales by full C!)

    for (int c0 = 0; c0 < SEQ; c0 += 64) {
        __syncthreads();   // prior iteration finished with Ks/Vs
        // ---- load K,V chunk (64x64 each), tf32-converted ----
        for (int i = tid; i < 64 * 16; i += 256) {
            int row = i >> 4, seg = i & 15;
            size_t go = base + (size_t)(c0 + row) * 3072;
            float4 kv = *(const float4*)&qkv[go + EMB + seg * 4];
            float4 vv = *(const float4*)&qkv[go + 2 * EMB + seg * 4];
            float* dk = &Ks[row * KS_STRIDE + seg * 4];
            dk[0] = to_tf32(kv.x); dk[1] = to_tf32(kv.y);
            dk[2] = to_tf32(kv.z); dk[3] = to_tf32(kv.w);
            float* dv = &Vs[row * VS_STRIDE + seg * 4];
            dv[0] = to_tf32(vv.x); dv[1] = to_tf32(vv.y);
            dv[2] = to_tf32(vv.z); dv[3] = to_tf32(vv.w);
        }
        __syncthreads();

        // ---- S = Q K^T (16 x 64 per warp) ----
        float s[8][4];
#pragma unroll
        for (int ni = 0; ni < 8; ni++)
#pragma unroll
            for (int j = 0; j < 4; j++) s[ni][j] = 0.0f;
#pragma unroll
        for (int kd = 0; kd < 8; kd++) {
#pragma unroll
            for (int ni = 0; ni < 8; ni++) {
                float bfr[2];
                int key = ni * 8 + lg;
                bfr[0] = Ks[key * KS_STRIDE + kd * 8 + lt];
                bfr[1] = Ks[key * KS_STRIDE + kd * 8 + lt + 4];
                mma_tf32(s[ni], aq[kd], bfr);
            }
        }

        // ---- online softmax (rows r = lane>>2 and r+8 of this warp tile) ----
        float mr0 = -INFINITY, mr1 = -INFINITY;
#pragma unroll
        for (int ni = 0; ni < 8; ni++) {
            mr0 = fmaxf(mr0, fmaxf(s[ni][0], s[ni][1]));
            mr1 = fmaxf(mr1, fmaxf(s[ni][2], s[ni][3]));
        }
#pragma unroll
        for (int off = 1; off <= 2; off <<= 1) {
            mr0 = fmaxf(mr0, __shfl_xor_sync(0xffffffffu, mr0, off));
            mr1 = fmaxf(mr1, __shfl_xor_sync(0xffffffffu, mr1, off));
        }
        float mn0 = fmaxf(m0r, mr0 * scale);
        float mn1 = fmaxf(m1r, mr1 * scale);
        float f0 = __expf(m0r - mn0);
        float f1 = __expf(m1r - mn1);
        m0r = mn0; m1r = mn1;

        int pr = warp * 16 + lg;
        float rs0 = 0.0f, rs1 = 0.0f;
#pragma unroll
        for (int ni = 0; ni < 8; ni++) {
            float p0 = __expf(s[ni][0] * scale - mn0);
            float p1 = __expf(s[ni][1] * scale - mn0);
            float p2 = __expf(s[ni][2] * scale - mn1);
            float p3 = __expf(s[ni][3] * scale - mn1);
            rs0 += p0 + p1;
            rs1 += p2 + p3;
            int col = ni * 8 + 2 * lt;
            *(float2*)&Ps[pr * PS_STRIDE + col] =
                make_float2(to_tf32(p0), to_tf32(p1));
            *(float2*)&Ps[(pr + 8) * PS_STRIDE + col] =
                make_float2(to_tf32(p2), to_tf32(p3));
            // rescale O accumulators
            o[ni][0] *= f0; o[ni][1] *= f0;
            o[ni][2] *= f1; o[ni][3] *= f1;
        }
#pragma unroll
        for (int off = 1; off <= 2; off <<= 1) {
            rs0 += __shfl_xor_sync(0xffffffffu, rs0, off);
            rs1 += __shfl_xor_sync(0xffffffffu, rs1, off);
        }
        l0 = l0 * f0 + rs0;
        l1 = l1 * f1 + rs1;
        __syncwarp();

        // ---- O += P V  (K-dim = 64 keys) ----
#pragma unroll
        for (int kk = 0; kk < 8; kk++) {
            float pa[4];
            int col = kk * 8 + lt;
            pa[0] = Ps[pr * PS_STRIDE + col];
            pa[1] = Ps[(pr + 8) * PS_STRIDE + col];
            pa[2] = Ps[pr * PS_STRIDE + col + 4];
            pa[3] = Ps[(pr + 8) * PS_STRIDE + col + 4];
#pragma unroll
            for (int ni = 0; ni < 8; ni++) {
                float bfr[2];
                int d = ni * 8 + lg;
                bfr[0] = Vs[(kk * 8 + lt) * VS_STRIDE + d];
                bfr[1] = Vs[(kk * 8 + lt + 4) * VS_STRIDE + d];
                mma_tf32(o[ni], pa, bfr);
            }
        }
        __syncwarp();
    }

    // ---- normalize and write [B,N,C] ----
    float inv0 = 1.0f / l0, inv1 = 1.0f / l1;
    int r = q0 + warp * 16 + lg;
#pragma unroll
    for (int ni = 0; ni < 8; ni++) {
        int col = h * HDIM + ni * 8 + 2 * lt;
        *(float2*)&out[((size_t)b * SEQ + r) * EMB + col] =
            make_float2(o[ni][0] * inv0, o[ni][1] * inv0);
        *(float2*)&out[((size_t)b * SEQ + r + 8) * EMB + col] =
            make_float2(o[ni][2] * inv1, o[ni][3] * inv1);
    }
}

// ---------------------------------------------------------------------------
extern "C" void kernel_launch(void* const* d_in, const int* in_sizes, int n_in,
                              void* d_out, int out_size) {
    const float* x     = (const float*)d_in[0];
    const float* W_qkv = (const float*)d_in[1];
    const float* b_qkv = (const float*)d_in[2];
    const float* W_out = (const float*)d_in[3];
    const float* b_out = (const float*)d_in[4];
    float* out = (float*)d_out;

    float* qkv;
    float* attn;
    cudaGetSymbolAddress((void**)&qkv, g_qkv);
    cudaGetSymbolAddress((void**)&attn, g_attn);

    cudaFuncSetAttribute(attn_tf32_kernel,
                         cudaFuncAttributeMaxDynamicSharedMemorySize,
                         ATTN_SMEM_BYTES);

    // 1) QKV projection
    gemm_tf32_kernel<<<dim3(QKV_N / 128, M_TOT / 128), 256>>>(
        x, W_qkv, b_qkv, qkv, M_TOT, QKV_N, EMB);
    // 2) Attention
    attn_tf32_kernel<<<dim3(SEQ / 128, BATCH * HEADS), 256, ATTN_SMEM_BYTES>>>(
        qkv, attn);
    // 3) Output projection
    gemm_tf32_kernel<<<dim3(EMB / 128, M_TOT / 128), 256>>>(
        attn, W_out, b_out, out, M_TOT, EMB, EMB);
}

// round 3
// speedup vs baseline: 3.3371x; 1.2529x over previous
#include <cuda_runtime.h>
#include <math.h>
#include <stdint.h>

#define BATCH 2
#define SEQ   2048
#define EMB   1024
#define HEADS 16
#define HDIM  64
#define M_TOT (BATCH * SEQ)   // 4096
#define QKV_N (3 * EMB)       // 3072

__device__ float g_qkv[M_TOT * QKV_N];      // [B,N,3,H,D]
__device__ float g_attn[M_TOT * EMB];       // [B,N,C]

__device__ __forceinline__ float to_tf32(float x) {
    uint32_t r;
    asm("cvt.rna.tf32.f32 %0, %1;" : "=r"(r) : "r"(__float_as_uint(x)));
    return __uint_as_float(r);
}

__device__ __forceinline__ void mma_tf32(float* c, const float* a, const float* b) {
    const uint32_t* A = (const uint32_t*)a;
    const uint32_t* B = (const uint32_t*)b;
    asm volatile(
        "mma.sync.aligned.m16n8k8.row.col.f32.tf32.tf32.f32 "
        "{%0,%1,%2,%3},{%4,%5,%6,%7},{%8,%9},{%0,%1,%2,%3};"
        : "+f"(c[0]), "+f"(c[1]), "+f"(c[2]), "+f"(c[3])
        : "r"(A[0]), "r"(A[1]), "r"(A[2]), "r"(A[3]), "r"(B[0]), "r"(B[1]));
}

// ---------------------------------------------------------------------------
// TF32 GEMM: C = A[M,K] @ B[K,N] + bias. Block 256x128, warp tile 64x64,
// K-tile 16, 2-stage smem double buffer + register prefetch.
// ---------------------------------------------------------------------------
#define AS_STRIDE 20
#define BS_STRIDE 136
#define AS_FLOATS (256 * AS_STRIDE)            // 5120
#define BS_FLOATS (16 * BS_STRIDE)             // 2176
#define GM_STAGE  (AS_FLOATS + BS_FLOATS)      // 7296 floats
#define GEMM_SMEM_BYTES (GM_STAGE * 2 * 4)     // 58368 B

__global__ __launch_bounds__(256, 1)
void gemm_tf32_kernel(const float* __restrict__ A, const float* __restrict__ B,
                      const float* __restrict__ bias, float* __restrict__ C,
                      int M, int N, int K) {
    extern __shared__ float sm[];

    const int tid  = threadIdx.x;
    const int lane = tid & 31;
    const int warp = tid >> 5;
    const int wm = (warp >> 1) * 64;   // 0,64,128,192
    const int wn = (warp & 1) * 64;    // 0,64
    const int m0 = blockIdx.y * 256;
    const int n0 = blockIdx.x * 128;
    const int lg = lane >> 2;
    const int lt = lane & 3;

    float c[4][8][4];
#pragma unroll
    for (int mi = 0; mi < 4; mi++)
#pragma unroll
        for (int ni = 0; ni < 8; ni++)
#pragma unroll
            for (int j = 0; j < 4; j++) c[mi][ni][j] = 0.0f;

    float4 ra[4], rb[2];

    auto ldg = [&](int kt) {
        const int k0 = kt * 16;
#pragma unroll
        for (int r = 0; r < 4; r++) {
            int i = tid + r * 256, row = i >> 2, seg = i & 3;
            ra[r] = *(const float4*)&A[(size_t)(m0 + row) * K + k0 + seg * 4];
        }
#pragma unroll
        for (int r = 0; r < 2; r++) {
            int i = tid + r * 256, row = i >> 5, seg = i & 31;
            rb[r] = *(const float4*)&B[(size_t)(k0 + row) * N + n0 + seg * 4];
        }
    };
    auto sts = [&](int s) {
        float* As = sm + s * GM_STAGE;
        float* Bs = As + AS_FLOATS;
#pragma unroll
        for (int r = 0; r < 4; r++) {
            int i = tid + r * 256, row = i >> 2, seg = i & 3;
            float* d = &As[row * AS_STRIDE + seg * 4];
            d[0] = to_tf32(ra[r].x); d[1] = to_tf32(ra[r].y);
            d[2] = to_tf32(ra[r].z); d[3] = to_tf32(ra[r].w);
        }
#pragma unroll
        for (int r = 0; r < 2; r++) {
            int i = tid + r * 256, row = i >> 5, seg = i & 31;
            float* d = &Bs[row * BS_STRIDE + seg * 4];
            d[0] = to_tf32(rb[r].x); d[1] = to_tf32(rb[r].y);
            d[2] = to_tf32(rb[r].z); d[3] = to_tf32(rb[r].w);
        }
    };

    const int NKT = K / 16;
    ldg(0);
    sts(0);
    ldg(1);
    __syncthreads();

    for (int t = 0; t < NKT; t++) {
        if (t + 1 < NKT) sts((t + 1) & 1);
        if (t + 2 < NKT) ldg(t + 2);

        const float* As = sm + (t & 1) * GM_STAGE;
        const float* Bs = As + AS_FLOATS;
#pragma unroll
        for (int ks = 0; ks < 2; ks++) {
            const int kk = ks * 8;
            float a[4][4];
#pragma unroll
            for (int mi = 0; mi < 4; mi++) {
                int row = wm + mi * 16 + lg;
                int col = kk + lt;
                a[mi][0] = As[row * AS_STRIDE + col];
                a[mi][1] = As[(row + 8) * AS_STRIDE + col];
                a[mi][2] = As[row * AS_STRIDE + col + 4];
                a[mi][3] = As[(row + 8) * AS_STRIDE + col + 4];
            }
#pragma unroll
            for (int ni = 0; ni < 8; ni++) {
                float b[2];
                int col = wn + ni * 8 + lg;
                b[0] = Bs[(kk + lt) * BS_STRIDE + col];
                b[1] = Bs[(kk + lt + 4) * BS_STRIDE + col];
#pragma unroll
                for (int mi = 0; mi < 4; mi++) mma_tf32(c[mi][ni], a[mi], b);
            }
        }
        __syncthreads();
    }

#pragma unroll
    for (int mi = 0; mi < 4; mi++) {
        int row = m0 + wm + mi * 16 + lg;
#pragma unroll
        for (int ni = 0; ni < 8; ni++) {
            int col = n0 + wn + ni * 8 + 2 * lt;
            float2 bv = *(const float2*)&bias[col];
            *(float2*)&C[(size_t)row * N + col] =
                make_float2(c[mi][ni][0] + bv.x, c[mi][ni][1] + bv.y);
            *(float2*)&C[(size_t)(row + 8) * N + col] =
                make_float2(c[mi][ni][2] + bv.x, c[mi][ni][3] + bv.y);
        }
    }
}

// ---------------------------------------------------------------------------
// Flash attention, TF32. Grid (SEQ/128, B*H), 256 thr = 8 warps x 16 q-rows.
// Br=128, Bc=64. Double-buffered K/V + register prefetch. P fragments built
// from S fragments via warp shuffles (no smem round-trip).
// ---------------------------------------------------------------------------
#define KSS 68
#define VSS 72
#define AT_KF (64 * KSS)            // 4352
#define AT_VF (64 * VSS)            // 4608
#define AT_STAGE (AT_KF + AT_VF)    // 8960 floats
#define ATTN_SMEM_BYTES (AT_STAGE * 2 * 4)   // 71680 B
#define QS 68

__global__ __launch_bounds__(256, 1)
void attn_tf32_kernel(const float* __restrict__ qkv, float* __restrict__ out) {
    extern __shared__ float sm[];

    const int tid  = threadIdx.x;
    const int lane = tid & 31;
    const int warp = tid >> 5;
    const int lg = lane >> 2;
    const int lt = lane & 3;
    const int bh = blockIdx.y;
    const int b  = bh >> 4;
    const int h  = bh & 15;
    const int q0 = blockIdx.x * 128;
    const unsigned FULL = 0xffffffffu;

    const size_t base = (size_t)b * SEQ * 3 * EMB + (size_t)h * HDIM;

    float4 kreg[4], vreg[4];
    auto ldg = [&](int it) {
        const int c0 = it * 64;
#pragma unroll
        for (int r = 0; r < 4; r++) {
            int i = tid + r * 256, row = i >> 4, seg = i & 15;
            size_t go = base + (size_t)(c0 + row) * 3072;
            kreg[r] = *(const float4*)&qkv[go + EMB + seg * 4];
            vreg[r] = *(const float4*)&qkv[go + 2 * EMB + seg * 4];
        }
    };
    auto sts = [&](int s) {
        float* Ks = sm + s * AT_STAGE;
        float* Vs = Ks + AT_KF;
#pragma unroll
        for (int r = 0; r < 4; r++) {
            int i = tid + r * 256, row = i >> 4, seg = i & 15;
            float* dk = &Ks[row * KSS + seg * 4];
            dk[0] = to_tf32(kreg[r].x); dk[1] = to_tf32(kreg[r].y);
            dk[2] = to_tf32(kreg[r].z); dk[3] = to_tf32(kreg[r].w);
            float* dv = &Vs[row * VSS + seg * 4];
            dv[0] = to_tf32(vreg[r].x); dv[1] = to_tf32(vreg[r].y);
            dv[2] = to_tf32(vreg[r].z); dv[3] = to_tf32(vreg[r].w);
        }
    };

    // issue first K/V load early
    ldg(0);

    // ---- stage Q (128x64) into stage-0 region, extract fragments ----
    for (int i = tid; i < 128 * 16; i += 256) {
        int row = i >> 4, seg = i & 15;
        float4 v = *(const float4*)&qkv[base + (size_t)(q0 + row) * 3072 + seg * 4];
        float* d = &sm[row * QS + seg * 4];
        d[0] = to_tf32(v.x); d[1] = to_tf32(v.y);
        d[2] = to_tf32(v.z); d[3] = to_tf32(v.w);
    }
    __syncthreads();

    float aq[8][4];
    {
        int r = warp * 16 + lg;
#pragma unroll
        for (int kd = 0; kd < 8; kd++) {
            int col = kd * 8 + lt;
            aq[kd][0] = sm[r * QS + col];
            aq[kd][1] = sm[(r + 8) * QS + col];
            aq[kd][2] = sm[r * QS + col + 4];
            aq[kd][3] = sm[(r + 8) * QS + col + 4];
        }
    }
    __syncthreads();   // all warps done reading Q staging

    sts(0);
    ldg(1);
    __syncthreads();

    float o[8][4];
#pragma unroll
    for (int ni = 0; ni < 8; ni++)
#pragma unroll
        for (int j = 0; j < 4; j++) o[ni][j] = 0.0f;
    float m0r = -INFINITY, m1r = -INFINITY, l0 = 0.0f, l1 = 0.0f;
    const float scale = 0.03125f;  // EMB^-0.5 (reference uses full C)

    const int NIT = SEQ / 64;
    const int src0 = (lane & 28) | (lt >> 1);
    const int src2 = src0 + 2;
    const bool odd = lt & 1;

    for (int t = 0; t < NIT; t++) {
        if (t + 1 < NIT) sts((t + 1) & 1);
        if (t + 2 < NIT) ldg(t + 2);

        const float* Ks = sm + (t & 1) * AT_STAGE;
        const float* Vs = Ks + AT_KF;

        // ---- S = Q K^T (16 x 64 per warp) ----
        float s[8][4];
#pragma unroll
        for (int ni = 0; ni < 8; ni++)
#pragma unroll
            for (int j = 0; j < 4; j++) s[ni][j] = 0.0f;
#pragma unroll
        for (int kd = 0; kd < 8; kd++) {
#pragma unroll
            for (int ni = 0; ni < 8; ni++) {
                float bfr[2];
                int key = ni * 8 + lg;
                bfr[0] = Ks[key * KSS + kd * 8 + lt];
                bfr[1] = Ks[key * KSS + kd * 8 + lt + 4];
                mma_tf32(s[ni], aq[kd], bfr);
            }
        }

        // ---- online softmax ----
        float mr0 = -INFINITY, mr1 = -INFINITY;
#pragma unroll
        for (int ni = 0; ni < 8; ni++) {
            mr0 = fmaxf(mr0, fmaxf(s[ni][0], s[ni][1]));
            mr1 = fmaxf(mr1, fmaxf(s[ni][2], s[ni][3]));
        }
#pragma unroll
        for (int off = 1; off <= 2; off <<= 1) {
            mr0 = fmaxf(mr0, __shfl_xor_sync(FULL, mr0, off));
            mr1 = fmaxf(mr1, __shfl_xor_sync(FULL, mr1, off));
        }
        float mn0 = fmaxf(m0r, mr0 * scale);
        float mn1 = fmaxf(m1r, mr1 * scale);
        float f0 = __expf(m0r - mn0);
        float f1 = __expf(m1r - mn1);
        m0r = mn0; m1r = mn1;

        float rs0 = 0.0f, rs1 = 0.0f;
#pragma unroll
        for (int ni = 0; ni < 8; ni++) {
            float p0 = __expf(s[ni][0] * scale - mn0);
            float p1 = __expf(s[ni][1] * scale - mn0);
            float p2 = __expf(s[ni][2] * scale - mn1);
            float p3 = __expf(s[ni][3] * scale - mn1);
            rs0 += p0 + p1;
            rs1 += p2 + p3;
            s[ni][0] = to_tf32(p0); s[ni][1] = to_tf32(p1);
            s[ni][2] = to_tf32(p2); s[ni][3] = to_tf32(p3);
            o[ni][0] *= f0; o[ni][1] *= f0;
            o[ni][2] *= f1; o[ni][3] *= f1;
        }
#pragma unroll
        for (int off = 1; off <= 2; off <<= 1) {
            rs0 += __shfl_xor_sync(FULL, rs0, off);
            rs1 += __shfl_xor_sync(FULL, rs1, off);
        }
        l0 = l0 * f0 + rs0;
        l1 = l1 * f1 + rs1;

        // ---- O += P V; P a-fragments via shuffles from S c-fragments ----
#pragma unroll
        for (int kk = 0; kk < 8; kk++) {
            float v00 = __shfl_sync(FULL, s[kk][0], src0);
            float v01 = __shfl_sync(FULL, s[kk][1], src0);
            float v02 = __shfl_sync(FULL, s[kk][2], src0);
            float v03 = __shfl_sync(FULL, s[kk][3], src0);
            float v20 = __shfl_sync(FULL, s[kk][0], src2);
            float v21 = __shfl_sync(FULL, s[kk][1], src2);
            float v22 = __shfl_sync(FULL, s[kk][2], src2);
            float v23 = __shfl_sync(FULL, s[kk][3], src2);
            float pa[4];
            pa[0] = odd ? v01 : v00;   // P[lg   ][kk*8+lt  ]
            pa[1] = odd ? v03 : v02;   // P[lg+8 ][kk*8+lt  ]
            pa[2] = odd ? v21 : v20;   // P[lg   ][kk*8+lt+4]
            pa[3] = odd ? v23 : v22;   // P[lg+8 ][kk*8+lt+4]
#pragma unroll
            for (int ni = 0; ni < 8; ni++) {
                float bfr[2];
                int d = ni * 8 + lg;
                bfr[0] = Vs[(kk * 8 + lt) * VSS + d];
                bfr[1] = Vs[(kk * 8 + lt + 4) * VSS + d];
                mma_tf32(o[ni], pa, bfr);
            }
        }
        __syncthreads();
    }

    // ---- normalize, write [B,N,C] ----
    float inv0 = 1.0f / l0, inv1 = 1.0f / l1;
    int r = q0 + warp * 16 + lg;
#pragma unroll
    for (int ni = 0; ni < 8; ni++) {
        int col = h * HDIM + ni * 8 + 2 * lt;
        *(float2*)&out[((size_t)b * SEQ + r) * EMB + col] =
            make_float2(o[ni][0] * inv0, o[ni][1] * inv0);
        *(float2*)&out[((size_t)b * SEQ + r + 8) * EMB + col] =
            make_float2(o[ni][2] * inv1, o[ni][3] * inv1);
    }
}

// ---------------------------------------------------------------------------
extern "C" void kernel_launch(void* const* d_in, const int* in_sizes, int n_in,
                              void* d_out, int out_size) {
    const float* x     = (const float*)d_in[0];
    const float* W_qkv = (const float*)d_in[1];
    const float* b_qkv = (const float*)d_in[2];
    const float* W_out = (const float*)d_in[3];
    const float* b_out = (const float*)d_in[4];
    float* out = (float*)d_out;

    float* qkv;
    float* attn;
    cudaGetSymbolAddress((void**)&qkv, g_qkv);
    cudaGetSymbolAddress((void**)&attn, g_attn);

    cudaFuncSetAttribute(gemm_tf32_kernel,
                         cudaFuncAttributeMaxDynamicSharedMemorySize,
                         GEMM_SMEM_BYTES);
    cudaFuncSetAttribute(attn_tf32_kernel,
                         cudaFuncAttributeMaxDynamicSharedMemorySize,
                         ATTN_SMEM_BYTES);

    gemm_tf32_kernel<<<dim3(QKV_N / 128, M_TOT / 256), 256, GEMM_SMEM_BYTES>>>(
        x, W_qkv, b_qkv, qkv, M_TOT, QKV_N, EMB);
    attn_tf32_kernel<<<dim3(SEQ / 128, BATCH * HEADS), 256, ATTN_SMEM_BYTES>>>(
        qkv, attn);
    gemm_tf32_kernel<<<dim3(EMB / 128, M_TOT / 256), 256, GEMM_SMEM_BYTES>>>(
        attn, W_out, b_out, out, M_TOT, EMB, EMB);
}

// round 4
// speedup vs baseline: 3.6734x; 1.1008x over previous
#include <cuda_runtime.h>
#include <math.h>
#include <stdint.h>

#define BATCH 2
#define SEQ   2048
#define EMB   1024
#define HEADS 16
#define HDIM  64
#define M_TOT (BATCH * SEQ)   // 4096
#define QKV_N (3 * EMB)       // 3072

__device__ float g_qkv[M_TOT * QKV_N];      // [B,N,3,H,D] (tf32-rounded)
__device__ float g_attn[M_TOT * EMB];       // [B,N,C]     (tf32-rounded)
__device__ float g_xc[M_TOT * EMB];         // x, tf32-rounded
__device__ float g_wqkvc[EMB * QKV_N];      // W_qkv, tf32-rounded
__device__ float g_woutc[EMB * EMB];        // W_out, tf32-rounded

__device__ __forceinline__ float to_tf32(float x) {
    uint32_t r;
    asm("cvt.rna.tf32.f32 %0, %1;" : "=r"(r) : "r"(__float_as_uint(x)));
    return __uint_as_float(r);
}

__device__ __forceinline__ void mma_tf32(float* c, const float* a, const float* b) {
    const uint32_t* A = (const uint32_t*)a;
    const uint32_t* B = (const uint32_t*)b;
    asm volatile(
        "mma.sync.aligned.m16n8k8.row.col.f32.tf32.tf32.f32 "
        "{%0,%1,%2,%3},{%4,%5,%6,%7},{%8,%9},{%0,%1,%2,%3};"
        : "+f"(c[0]), "+f"(c[1]), "+f"(c[2]), "+f"(c[3])
        : "r"(A[0]), "r"(A[1]), "r"(A[2]), "r"(A[3]), "r"(B[0]), "r"(B[1]));
}

__device__ __forceinline__ uint32_t smem_u32(const void* p) {
    return (uint32_t)__cvta_generic_to_shared(p);
}
__device__ __forceinline__ void cp16(uint32_t s, const void* g) {
    asm volatile("cp.async.cg.shared.global [%0], [%1], 16;" :: "r"(s), "l"(g));
}
#define CP_COMMIT() asm volatile("cp.async.commit_group;")
#define CP_WAIT2()  asm volatile("cp.async.wait_group 2;")
#define CP_WAIT3()  asm volatile("cp.async.wait_group 3;")

// ---------------------------------------------------------------------------
// tf32 rounding (elementwise, float4)
// ---------------------------------------------------------------------------
__global__ void cvt_tf32_kernel(const float4* __restrict__ in,
                                float4* __restrict__ out, int n4) {
    int i = blockIdx.x * blockDim.x + threadIdx.x;
    if (i < n4) {
        float4 v = in[i];
        v.x = to_tf32(v.x); v.y = to_tf32(v.y);
        v.z = to_tf32(v.z); v.w = to_tf32(v.w);
        out[i] = v;
    }
}

// ---------------------------------------------------------------------------
// TF32 GEMM: C = A[M,K] @ B[K,N] + bias. A,B already tf32-rounded.
// Block 256x128, warp tile 64x64, K-tile 16, 3-stage cp.async pipeline.
// ---------------------------------------------------------------------------
#define AS_STRIDE 20
#define BS_STRIDE 136
#define AS_FLOATS (256 * AS_STRIDE)            // 5120
#define BS_FLOATS (16 * BS_STRIDE)             // 2176
#define GM_STAGE  (AS_FLOATS + BS_FLOATS)      // 7296 floats
#define GEMM_SMEM_BYTES (GM_STAGE * 3 * 4)     // 87552 B

__global__ __launch_bounds__(256, 1)
void gemm_tf32_kernel(const float* __restrict__ A, const float* __restrict__ B,
                      const float* __restrict__ bias, float* __restrict__ C,
                      int M, int N, int K, int round_out) {
    extern __shared__ float sm[];

    const int tid  = threadIdx.x;
    const int lane = tid & 31;
    const int warp = tid >> 5;
    const int wm = (warp >> 1) * 64;
    const int wn = (warp & 1) * 64;
    const int m0 = blockIdx.y * 256;
    const int n0 = blockIdx.x * 128;
    const int lg = lane >> 2;
    const int lt = lane & 3;

    float c[4][8][4];
#pragma unroll
    for (int mi = 0; mi < 4; mi++)
#pragma unroll
        for (int ni = 0; ni < 8; ni++)
#pragma unroll
            for (int j = 0; j < 4; j++) c[mi][ni][j] = 0.0f;

    // per-thread load coordinates (A: 4 chunks, B: 2 chunks)
    const int a_row = tid >> 2, a_seg = tid & 3;       // +64-row steps
    const int b_row = tid >> 5, b_seg = tid & 31;      // +8-row steps

    auto ldg_stage = [&](int s, int kt) {
        const int k0 = kt * 16;
        float* As = sm + s * GM_STAGE;
        float* Bs = As + AS_FLOATS;
#pragma unroll
        for (int r = 0; r < 4; r++) {
            int row = a_row + r * 64;
            cp16(smem_u32(&As[row * AS_STRIDE + a_seg * 4]),
                 &A[(size_t)(m0 + row) * K + k0 + a_seg * 4]);
        }
#pragma unroll
        for (int r = 0; r < 2; r++) {
            int row = b_row + r * 8;
            cp16(smem_u32(&Bs[row * BS_STRIDE + b_seg * 4]),
                 &B[(size_t)(k0 + row) * N + n0 + b_seg * 4]);
        }
        CP_COMMIT();
    };

    const int NKT = K / 16;
    ldg_stage(0, 0);
    ldg_stage(1, 1);
    ldg_stage(2, 2);

    for (int t = 0; t < NKT; t++) {
        CP_WAIT2();
        __syncthreads();

        const float* As = sm + (t % 3) * GM_STAGE;
        const float* Bs = As + AS_FLOATS;
#pragma unroll
        for (int ks = 0; ks < 2; ks++) {
            const int kk = ks * 8;
            float a[4][4];
#pragma unroll
            for (int mi = 0; mi < 4; mi++) {
                int row = wm + mi * 16 + lg;
                int col = kk + lt;
                a[mi][0] = As[row * AS_STRIDE + col];
                a[mi][1] = As[(row + 8) * AS_STRIDE + col];
                a[mi][2] = As[row * AS_STRIDE + col + 4];
                a[mi][3] = As[(row + 8) * AS_STRIDE + col + 4];
            }
#pragma unroll
            for (int ni = 0; ni < 8; ni++) {
                float b[2];
                int col = wn + ni * 8 + lg;
                b[0] = Bs[(kk + lt) * BS_STRIDE + col];
                b[1] = Bs[(kk + lt + 4) * BS_STRIDE + col];
#pragma unroll
                for (int mi = 0; mi < 4; mi++) mma_tf32(c[mi][ni], a[mi], b);
            }
        }
        __syncthreads();
        if (t + 3 < NKT) ldg_stage(t % 3, t + 3);
        else CP_COMMIT();   // empty group keeps wait_group accounting exact
    }

#pragma unroll
    for (int mi = 0; mi < 4; mi++) {
        int row = m0 + wm + mi * 16 + lg;
#pragma unroll
        for (int ni = 0; ni < 8; ni++) {
            int col = n0 + wn + ni * 8 + 2 * lt;
            float2 bv = *(const float2*)&bias[col];
            float2 r0 = make_float2(c[mi][ni][0] + bv.x, c[mi][ni][1] + bv.y);
            float2 r1 = make_float2(c[mi][ni][2] + bv.x, c[mi][ni][3] + bv.y);
            if (round_out) {
                r0.x = to_tf32(r0.x); r0.y = to_tf32(r0.y);
                r1.x = to_tf32(r1.x); r1.y = to_tf32(r1.y);
            }
            *(float2*)&C[(size_t)row * N + col] = r0;
            *(float2*)&C[(size_t)(row + 8) * N + col] = r1;
        }
    }
}

// ---------------------------------------------------------------------------
// Flash attention, TF32. qkv already tf32-rounded. Br=128, Bc=64,
// 3-stage cp.async K/V pipeline, P fragments via shuffles. Output rounded.
// ---------------------------------------------------------------------------
#define KSS 68
#define VSS 72
#define AT_KF (64 * KSS)
#define AT_VF (64 * VSS)
#define AT_STAGE (AT_KF + AT_VF)                 // 8960 floats
#define QS 68
#define Q_OFF (AT_STAGE * 3)
#define ATTN_SMEM_BYTES ((AT_STAGE * 3 + 128 * QS) * 4)   // 142336 B

__global__ __launch_bounds__(256, 1)
void attn_tf32_kernel(const float* __restrict__ qkv, float* __restrict__ out) {
    extern __shared__ float sm[];

    const int tid  = threadIdx.x;
    const int lane = tid & 31;
    const int warp = tid >> 5;
    const int lg = lane >> 2;
    const int lt = lane & 3;
    const int bh = blockIdx.y;
    const int b  = bh >> 4;
    const int h  = bh & 15;
    const int q0 = blockIdx.x * 128;
    const unsigned FULL = 0xffffffffu;

    const size_t base = (size_t)b * SEQ * 3 * EMB + (size_t)h * HDIM;

    // per-thread K/V load coords: 64 rows x 16 chunks each -> 4 per thread each
    const int kv_row = tid >> 2, kv_seg = tid & 3;   // rows step +... (tid:0..255 -> row 0..63 x seg? 64*16=1024 chunks; tid covers 256, 4 iters)

    auto ldg_stage = [&](int s, int it) {
        const int c0 = it * 64;
        float* Ks = sm + s * AT_STAGE;
        float* Vs = Ks + AT_KF;
#pragma unroll
        for (int r = 0; r < 4; r++) {
            int i = tid + r * 256;
            int row = i >> 4, seg = i & 15;
            size_t go = base + (size_t)(c0 + row) * 3072;
            cp16(smem_u32(&Ks[row * KSS + seg * 4]), &qkv[go + EMB + seg * 4]);
            cp16(smem_u32(&Vs[row * VSS + seg * 4]), &qkv[go + 2 * EMB + seg * 4]);
        }
        CP_COMMIT();
    };

    // ---- Q via cp.async into its own region ----
    {
        float* Qs = sm + Q_OFF;
#pragma unroll
        for (int r = 0; r < 8; r++) {
            int i = tid + r * 256;
            int row = i >> 4, seg = i & 15;
            cp16(smem_u32(&Qs[row * QS + seg * 4]),
                 &qkv[base + (size_t)(q0 + row) * 3072 + seg * 4]);
        }
        CP_COMMIT();
    }
    ldg_stage(0, 0);
    ldg_stage(1, 1);
    ldg_stage(2, 2);

    // wait for Q (4 groups pending -> <=3 means Q done), then extract frags
    CP_WAIT3();
    __syncthreads();

    float aq[8][4];
    {
        const float* Qs = sm + Q_OFF;
        int r = warp * 16 + lg;
#pragma unroll
        for (int kd = 0; kd < 8; kd++) {
            int col = kd * 8 + lt;
            aq[kd][0] = Qs[r * QS + col];
            aq[kd][1] = Qs[(r + 8) * QS + col];
            aq[kd][2] = Qs[r * QS + col + 4];
            aq[kd][3] = Qs[(r + 8) * QS + col + 4];
        }
    }

    float o[8][4];
#pragma unroll
    for (int ni = 0; ni < 8; ni++)
#pragma unroll
        for (int j = 0; j < 4; j++) o[ni][j] = 0.0f;
    float m0r = -INFINITY, m1r = -INFINITY, l0 = 0.0f, l1 = 0.0f;
    const float scale = 0.03125f;  // EMB^-0.5 (reference scales by full C)

    const int NIT = SEQ / 64;
    const int src0 = (lane & 28) | (lt >> 1);
    const int src2 = src0 + 2;
    const bool odd = lt & 1;

    for (int t = 0; t < NIT; t++) {
        CP_WAIT2();
        __syncthreads();

        const float* Ks = sm + (t % 3) * AT_STAGE;
        const float* Vs = Ks + AT_KF;

        // ---- S = Q K^T ----
        float s[8][4];
#pragma unroll
        for (int ni = 0; ni < 8; ni++)
#pragma unroll
            for (int j = 0; j < 4; j++) s[ni][j] = 0.0f;
#pragma unroll
        for (int kd = 0; kd < 8; kd++) {
#pragma unroll
            for (int ni = 0; ni < 8; ni++) {
                float bfr[2];
                int key = ni * 8 + lg;
                bfr[0] = Ks[key * KSS + kd * 8 + lt];
                bfr[1] = Ks[key * KSS + kd * 8 + lt + 4];
                mma_tf32(s[ni], aq[kd], bfr);
            }
        }

        // ---- online softmax ----
        float mr0 = -INFINITY, mr1 = -INFINITY;
#pragma unroll
        for (int ni = 0; ni < 8; ni++) {
            mr0 = fmaxf(mr0, fmaxf(s[ni][0], s[ni][1]));
            mr1 = fmaxf(mr1, fmaxf(s[ni][2], s[ni][3]));
        }
#pragma unroll
        for (int off = 1; off <= 2; off <<= 1) {
            mr0 = fmaxf(mr0, __shfl_xor_sync(FULL, mr0, off));
            mr1 = fmaxf(mr1, __shfl_xor_sync(FULL, mr1, off));
        }
        float mn0 = fmaxf(m0r, mr0 * scale);
        float mn1 = fmaxf(m1r, mr1 * scale);
        float f0 = __expf(m0r - mn0);
        float f1 = __expf(m1r - mn1);
        m0r = mn0; m1r = mn1;

        float rs0 = 0.0f, rs1 = 0.0f;
#pragma unroll
        for (int ni = 0; ni < 8; ni++) {
            float p0 = __expf(s[ni][0] * scale - mn0);
            float p1 = __expf(s[ni][1] * scale - mn0);
            float p2 = __expf(s[ni][2] * scale - mn1);
            float p3 = __expf(s[ni][3] * scale - mn1);
            rs0 += p0 + p1;
            rs1 += p2 + p3;
            s[ni][0] = to_tf32(p0); s[ni][1] = to_tf32(p1);
            s[ni][2] = to_tf32(p2); s[ni][3] = to_tf32(p3);
            o[ni][0] *= f0; o[ni][1] *= f0;
            o[ni][2] *= f1; o[ni][3] *= f1;
        }
#pragma unroll
        for (int off = 1; off <= 2; off <<= 1) {
            rs0 += __shfl_xor_sync(FULL, rs0, off);
            rs1 += __shfl_xor_sync(FULL, rs1, off);
        }
        l0 = l0 * f0 + rs0;
        l1 = l1 * f1 + rs1;

        // ---- O += P V ----
#pragma unroll
        for (int kk = 0; kk < 8; kk++) {
            float v00 = __shfl_sync(FULL, s[kk][0], src0);
            float v01 = __shfl_sync(FULL, s[kk][1], src0);
            float v02 = __shfl_sync(FULL, s[kk][2], src0);
            float v03 = __shfl_sync(FULL, s[kk][3], src0);
            float v20 = __shfl_sync(FULL, s[kk][0], src2);
            float v21 = __shfl_sync(FULL, s[kk][1], src2);
            float v22 = __shfl_sync(FULL, s[kk][2], src2);
            float v23 = __shfl_sync(FULL, s[kk][3], src2);
            float pa[4];
            pa[0] = odd ? v01 : v00;
            pa[1] = odd ? v03 : v02;
            pa[2] = odd ? v21 : v20;
            pa[3] = odd ? v23 : v22;
#pragma unroll
            for (int ni = 0; ni < 8; ni++) {
                float bfr[2];
                int d = ni * 8 + lg;
                bfr[0] = Vs[(kk * 8 + lt) * VSS + d];
                bfr[1] = Vs[(kk * 8 + lt + 4) * VSS + d];
                mma_tf32(o[ni], pa, bfr);
            }
        }
        __syncthreads();
        if (t + 3 < NIT) ldg_stage(t % 3, t + 3);
        else CP_COMMIT();
    }

    // ---- normalize, round to tf32 (GEMM3 consumes), write [B,N,C] ----
    float inv0 = 1.0f / l0, inv1 = 1.0f / l1;
    int r = q0 + warp * 16 + lg;
#pragma unroll
    for (int ni = 0; ni < 8; ni++) {
        int col = h * HDIM + ni * 8 + 2 * lt;
        *(float2*)&out[((size_t)b * SEQ + r) * EMB + col] =
            make_float2(to_tf32(o[ni][0] * inv0), to_tf32(o[ni][1] * inv0));
        *(float2*)&out[((size_t)b * SEQ + r + 8) * EMB + col] =
            make_float2(to_tf32(o[ni][2] * inv1), to_tf32(o[ni][3] * inv1));
    }
}

// ---------------------------------------------------------------------------
extern "C" void kernel_launch(void* const* d_in, const int* in_sizes, int n_in,
                              void* d_out, int out_size) {
    const float* x     = (const float*)d_in[0];
    const float* W_qkv = (const float*)d_in[1];
    const float* b_qkv = (const float*)d_in[2];
    const float* W_out = (const float*)d_in[3];
    const float* b_out = (const float*)d_in[4];
    float* out = (float*)d_out;

    float *qkv, *attn, *xc, *wqkvc, *woutc;
    cudaGetSymbolAddress((void**)&qkv, g_qkv);
    cudaGetSymbolAddress((void**)&attn, g_attn);
    cudaGetSymbolAddress((void**)&xc, g_xc);
    cudaGetSymbolAddress((void**)&wqkvc, g_wqkvc);
    cudaGetSymbolAddress((void**)&woutc, g_woutc);

    cudaFuncSetAttribute(gemm_tf32_kernel,
                         cudaFuncAttributeMaxDynamicSharedMemorySize,
                         GEMM_SMEM_BYTES);
    cudaFuncSetAttribute(attn_tf32_kernel,
                         cudaFuncAttributeMaxDynamicSharedMemorySize,
                         ATTN_SMEM_BYTES);

    // 0) tf32-round inputs once (cheap, memory-bound)
    {
        int n4;
        n4 = M_TOT * EMB / 4;
        cvt_tf32_kernel<<<(n4 + 255) / 256, 256>>>((const float4*)x, (float4*)xc, n4);
        n4 = EMB * QKV_N / 4;
        cvt_tf32_kernel<<<(n4 + 255) / 256, 256>>>((const float4*)W_qkv, (float4*)wqkvc, n4);
        n4 = EMB * EMB / 4;
        cvt_tf32_kernel<<<(n4 + 255) / 256, 256>>>((const float4*)W_out, (float4*)woutc, n4);
    }

    // 1) QKV projection (epilogue rounds output for attention)
    gemm_tf32_kernel<<<dim3(QKV_N / 128, M_TOT / 256), 256, GEMM_SMEM_BYTES>>>(
        xc, wqkvc, b_qkv, qkv, M_TOT, QKV_N, EMB, 1);
    // 2) Attention (epilogue rounds output for GEMM3)
    attn_tf32_kernel<<<dim3(SEQ / 128, BATCH * HEADS), 256, ATTN_SMEM_BYTES>>>(
        qkv, attn);
    // 3) Output projection (final fp32, no rounding)
    gemm_tf32_kernel<<<dim3(EMB / 128, M_TOT / 256), 256, GEMM_SMEM_BYTES>>>(
        attn, woutc, b_out, out, M_TOT, EMB, EMB, 0);
}